// round 1
// baseline (speedup 1.0000x reference)
#include <cuda_runtime.h>
#include <cstdint>

// ---------------------------------------------------------------------------
// Problem: N=10000 nodes, D=512 features, K=20 (keep top-21 per row).
//   h   = (relu(f*w0) * w1), L2-normalized per row
//   sim = h @ h^T                       (N x N)
//   keep top-(K+1) per row (ties -> lowest index), others become 0
//   out = elu(6*sim - 6) + 1   (non-kept: elu(-6)+1 = e^-6)
// d_out (N*N fp32) is used as scratch for sim, then transformed in place.
// ---------------------------------------------------------------------------

#define MAXN 10240
#define DIM  512
#define KKEEP 21

__device__ float g_h[MAXN * DIM];   // normalized features scratch (~21 MB)

// ------------------------- kernel 1: diag MLP + L2 normalize ---------------
__global__ __launch_bounds__(128) void norm_kernel(
    const float* __restrict__ f, const float* __restrict__ w0,
    const float* __restrict__ w1, int N)
{
    int row = blockIdx.x;
    if (row >= N) return;
    const float* fr = f + (size_t)row * DIM;
    float v[4];
    int t = threadIdx.x;
    float ss = 0.f;
#pragma unroll
    for (int i = 0; i < 4; i++) {
        int c = t + i * 128;
        float x = fr[c] * w0[c];
        x = x > 0.f ? x : 0.f;
        x *= w1[c];
        v[i] = x;
        ss += x * x;
    }
    // block reduction
    __shared__ float red[4];
#pragma unroll
    for (int o = 16; o > 0; o >>= 1) ss += __shfl_xor_sync(0xffffffffu, ss, o);
    if ((t & 31) == 0) red[t >> 5] = ss;
    __syncthreads();
    float tot = red[0] + red[1] + red[2] + red[3];
    float nrm = sqrtf(tot);
    float inv = 1.0f / fmaxf(nrm, 1e-12f);
    float* hr = g_h + (size_t)row * DIM;
#pragma unroll
    for (int i = 0; i < 4; i++) {
        int c = t + i * 128;
        hr[c] = v[i] * inv;
    }
}

// ------------------------- kernel 2: fp32 SIMT GEMM  C = H H^T -------------
#define BM 128
#define BN 128
#define BK 16
#define PAD 4

__global__ __launch_bounds__(256) void gemm_kernel(float* __restrict__ C, int N)
{
    __shared__ float As[BK][BM + PAD];
    __shared__ float Bs[BK][BN + PAD];

    const int bm = blockIdx.y * BM;
    const int bn = blockIdx.x * BN;
    const int tid = threadIdx.x;
    const int tx = tid & 15;        // 0..15 -> col octet
    const int ty = tid >> 4;        // 0..15 -> row octet

    float acc[8][8];
#pragma unroll
    for (int i = 0; i < 8; i++)
#pragma unroll
        for (int j = 0; j < 8; j++) acc[i][j] = 0.f;

    for (int k0 = 0; k0 < DIM; k0 += BK) {
        // cooperative load: 128 rows x 16 k for A and B, float4 per thread x2
#pragma unroll
        for (int p = 0; p < 2; p++) {
            int idx = tid + p * 256;          // 0..511 float4 slots
            int r   = idx >> 2;               // row in tile
            int kq  = (idx & 3) * 4;          // k offset
            int ga = bm + r;
            float4 va = (ga < N) ? *(const float4*)(g_h + (size_t)ga * DIM + k0 + kq)
                                 : make_float4(0.f, 0.f, 0.f, 0.f);
            As[kq + 0][r] = va.x; As[kq + 1][r] = va.y;
            As[kq + 2][r] = va.z; As[kq + 3][r] = va.w;
            int gb = bn + r;
            float4 vb = (gb < N) ? *(const float4*)(g_h + (size_t)gb * DIM + k0 + kq)
                                 : make_float4(0.f, 0.f, 0.f, 0.f);
            Bs[kq + 0][r] = vb.x; Bs[kq + 1][r] = vb.y;
            Bs[kq + 2][r] = vb.z; Bs[kq + 3][r] = vb.w;
        }
        __syncthreads();

#pragma unroll
        for (int k = 0; k < BK; k++) {
            float a[8], b[8];
            *(float4*)&a[0] = *(float4*)&As[k][ty * 8];
            *(float4*)&a[4] = *(float4*)&As[k][ty * 8 + 4];
            *(float4*)&b[0] = *(float4*)&Bs[k][tx * 8];
            *(float4*)&b[4] = *(float4*)&Bs[k][tx * 8 + 4];
#pragma unroll
            for (int i = 0; i < 8; i++)
#pragma unroll
                for (int j = 0; j < 8; j++) acc[i][j] = fmaf(a[i], b[j], acc[i][j]);
        }
        __syncthreads();
    }

    // store (float4, guarded)
#pragma unroll
    for (int i = 0; i < 8; i++) {
        int row = bm + ty * 8 + i;
        if (row >= N) continue;
        float* cr = C + (size_t)row * N;
#pragma unroll
        for (int j4 = 0; j4 < 2; j4++) {
            int col = bn + tx * 8 + j4 * 4;
            if (col + 3 < N) {
                float4 v = make_float4(acc[i][j4 * 4 + 0], acc[i][j4 * 4 + 1],
                                       acc[i][j4 * 4 + 2], acc[i][j4 * 4 + 3]);
                *(float4*)(cr + col) = v;
            } else {
#pragma unroll
                for (int j = 0; j < 4; j++)
                    if (col + j < N) cr[col + j] = acc[i][j4 * 4 + j];
            }
        }
    }
}

// ------------------------- kernel 3: per-row top-21 select + transform -----
__device__ __forceinline__ unsigned f2ord(float f) {
    unsigned u = __float_as_uint(f);
    return (u & 0x80000000u) ? ~u : (u | 0x80000000u);
}

__global__ __launch_bounds__(256) void topk_kernel(float* __restrict__ C, int N)
{
    __shared__ float srow[MAXN];
    __shared__ int hist[256];
    __shared__ unsigned sh_prefix;
    __shared__ int sh_need;
    __shared__ int eq_idx[64];
    __shared__ int eq_cnt;
    __shared__ int sh_cutoff;

    const int row = blockIdx.x;
    const int t = threadIdx.x;
    float* rowp = C + (size_t)row * N;

    for (int j = t; j < N; j += 256) srow[j] = rowp[j];
    __syncthreads();

    // --- radix select the 21st largest (exact, MSB-first over 4 bytes) ---
    unsigned prefix = 0;
    int need = KKEEP;
    for (int r = 0; r < 4; r++) {
        int shift = 24 - 8 * r;
        hist[t] = 0;
        __syncthreads();
        unsigned pmask = (r == 0) ? 0u : (0xFFFFFFFFu << (shift + 8));
        for (int j = t; j < N; j += 256) {
            unsigned key = f2ord(srow[j]);
            if ((key & pmask) == prefix)
                atomicAdd(&hist[(key >> shift) & 255], 1);
        }
        __syncthreads();
        if (t == 0) {
            int cum = 0, b = 255;
            for (; b >= 0; b--) { cum += hist[b]; if (cum >= need) break; }
            int higher = cum - hist[b];
            sh_need = need - higher;
            sh_prefix = prefix | ((unsigned)b << shift);
        }
        __syncthreads();
        prefix = sh_prefix;
        need = sh_need;
        __syncthreads();
    }
    const unsigned kth = prefix;   // exact key of 21st-largest value

    // --- tie handling: keep first `need` equal-valued entries by index ---
    if (t == 0) { eq_cnt = 0; sh_cutoff = N; }
    __syncthreads();
    for (int j = t; j < N; j += 256) {
        if (f2ord(srow[j]) == kth) {
            int p = atomicAdd(&eq_cnt, 1);
            if (p < 64) eq_idx[p] = j;
        }
    }
    __syncthreads();
    if (t == 0) {
        int E = eq_cnt;
        if (E <= need) {
            sh_cutoff = N;                      // keep all equals
        } else if (E <= 64) {
            for (int a = 1; a < E; a++) {       // insertion sort indices
                int v = eq_idx[a]; int b = a - 1;
                while (b >= 0 && eq_idx[b] > v) { eq_idx[b + 1] = eq_idx[b]; b--; }
                eq_idx[b + 1] = v;
            }
            sh_cutoff = eq_idx[need - 1];
        } else {                                // pathological: linear scan
            int cnt = 0, cut = N;
            for (int j = 0; j < N; j++)
                if (f2ord(srow[j]) == kth) { if (++cnt == need) { cut = j; break; } }
            sh_cutoff = cut;
        }
    }
    __syncthreads();
    const int cutoff = sh_cutoff;

    // --- transform + write back ---
    const float CBASE = expf(-6.0f);            // elu(-6)+1
    for (int j = t; j < N; j += 256) {
        float s = srow[j];
        unsigned key = f2ord(s);
        bool keep = (key > kth) || (key == kth && j <= cutoff);
        float o;
        if (keep) {
            float x = 6.0f * s - 6.0f;
            o = (x > 0.f) ? (x + 1.0f) : expf(x);
        } else {
            o = CBASE;
        }
        rowp[j] = o;
    }
}

// ---------------------------------------------------------------------------
extern "C" void kernel_launch(void* const* d_in, const int* in_sizes, int n_in,
                              void* d_out, int out_size)
{
    const float* features = (const float*)d_in[0];
    const float* w0 = (const float*)d_in[1];
    const float* w1 = (const float*)d_in[2];
    float* out = (float*)d_out;

    int D = in_sizes[1];           // 512
    int N = in_sizes[0] / D;       // 10000
    (void)n_in; (void)out_size;

    norm_kernel<<<N, 128>>>(features, w0, w1, N);

    dim3 ggrid((N + BN - 1) / BN, (N + BM - 1) / BM);
    gemm_kernel<<<ggrid, 256>>>(out, N);

    topk_kernel<<<N, 256>>>(out, N);
}

// round 3
// speedup vs baseline: 2.3010x; 2.3010x over previous
#include <cuda_runtime.h>
#include <cuda_bf16.h>
#include <cstdint>

// ---------------------------------------------------------------------------
// N=10000, D=512, K=20 (keep top-21 per row).
//   h = normalize(relu(f*w0)*w1)  -> split into bf16 hi/lo
//   sim = hi*hi^T + hi*lo^T + lo*hi^T  (mma.sync bf16, fp32 accum; ~fp32 exact)
//   symmetric: compute lower-triangle 128x128 tiles only, mirror via smem.
//   top-21 per row (ties -> lowest idx), others -> elu(-6)+1 = e^-6
// ---------------------------------------------------------------------------

#define MAXN 10240
#define DIM  512
#define KKEEP 21

__device__ __nv_bfloat16 g_hi[MAXN * DIM];
__device__ __nv_bfloat16 g_lo[MAXN * DIM];

__device__ __forceinline__ uint32_t smem_u32(const void* p) {
    uint32_t a;
    asm("{ .reg .u64 t; cvta.to.shared.u64 t, %1; cvt.u32.u64 %0, t; }"
        : "=r"(a) : "l"(p));
    return a;
}
#define SWZ(o) ((o) ^ (((o) >> 3) & 0x70))

// ------------------------- kernel 1: diag MLP + L2 normalize + split -------
__global__ __launch_bounds__(128) void norm_kernel(
    const float* __restrict__ f, const float* __restrict__ w0,
    const float* __restrict__ w1, int N)
{
    int row = blockIdx.x;
    if (row >= N) return;
    const float* fr = f + (size_t)row * DIM;
    float v[4];
    int t = threadIdx.x;
    float ss = 0.f;
#pragma unroll
    for (int i = 0; i < 4; i++) {
        int c = t + i * 128;
        float x = fr[c] * w0[c];
        x = x > 0.f ? x : 0.f;
        x *= w1[c];
        v[i] = x;
        ss += x * x;
    }
    __shared__ float red[4];
#pragma unroll
    for (int o = 16; o > 0; o >>= 1) ss += __shfl_xor_sync(0xffffffffu, ss, o);
    if ((t & 31) == 0) red[t >> 5] = ss;
    __syncthreads();
    float tot = red[0] + red[1] + red[2] + red[3];
    float inv = 1.0f / fmaxf(sqrtf(tot), 1e-12f);
#pragma unroll
    for (int i = 0; i < 4; i++) {
        int c = t + i * 128;
        float x = v[i] * inv;
        __nv_bfloat16 hi = __float2bfloat16(x);
        float hif = __bfloat162float(hi);
        __nv_bfloat16 lo = __float2bfloat16(x - hif);
        g_hi[(size_t)row * DIM + c] = hi;
        g_lo[(size_t)row * DIM + c] = lo;
    }
}

// ------------------------- kernel 2: mma.sync split-bf16 GEMM --------------
// BM=BN=128, KC=64 elems (128B rows), 2-stage cp.async pipeline.
// 8 warps: 4 (M) x 2 (N); warp tile 32x64; mma m16n8k16.
#define KC 64
#define A_STG 16384
#define STG 32768
#define CS_PITCH 129
#define GEMM_SMEM (128 * CS_PITCH * 4 + 256)   // >= 2*STG (65536); Cs overlay

#define LDSMX4(r0, r1, r2, r3, a) \
    asm volatile("ldmatrix.sync.aligned.m8n8.x4.shared.b16 {%0,%1,%2,%3}, [%4];" \
        : "=r"(r0), "=r"(r1), "=r"(r2), "=r"(r3) : "r"(a))

#define MMA16816(d, a, b0, b1) \
    asm volatile("mma.sync.aligned.m16n8k16.row.col.f32.bf16.bf16.f32 " \
        "{%0,%1,%2,%3}, {%4,%5,%6,%7}, {%8,%9}, {%0,%1,%2,%3};" \
        : "+f"((d)[0]), "+f"((d)[1]), "+f"((d)[2]), "+f"((d)[3]) \
        : "r"((a)[0]), "r"((a)[1]), "r"((a)[2]), "r"((a)[3]), "r"(b0), "r"(b1))

__global__ __launch_bounds__(256, 2) void gemm_mma(float* __restrict__ C, int N)
{
    extern __shared__ char smem[];
    const uint32_t sb = smem_u32(smem);

    // decode lower-triangular pair (bi >= bj)
    int x = blockIdx.x;
    int bi = (int)((sqrtf(8.f * (float)x + 1.f) - 1.f) * 0.5f);
    while ((bi + 1) * (bi + 2) / 2 <= x) bi++;
    while (bi * (bi + 1) / 2 > x) bi--;
    const int bj = x - bi * (bi + 1) / 2;
    const int bm = bi * 128;
    const int bn = bj * 128;

    const int tid = threadIdx.x;
    const int lane = tid & 31;
    const int wid = tid >> 5;
    const int wm = wid & 3;        // 0..3 -> 32-row slab
    const int wn = wid >> 2;       // 0..1 -> 64-col slab

    float acc[2][8][4];
#pragma unroll
    for (int mi = 0; mi < 2; mi++)
#pragma unroll
        for (int ni = 0; ni < 8; ni++)
#pragma unroll
            for (int q = 0; q < 4; q++) acc[mi][ni][q] = 0.f;

    // precompute ldmatrix lane addresses (byte offsets within tile buffers)
    const int g = lane >> 3;
    const int arow = wm * 32 + ((g & 1) * 8) + (lane & 7);      // + mi*16
    const int akb = (g >> 1) * 16;                              // + kk*32
    const int brow = wn * 64 + ((g >> 1) * 8) + (lane & 7);     // + p*16
    const int bkb = (g & 1) * 16;                               // + kk*32

    // producer: per chunk 2048 x 16B; thread handles 8
#define ISSUE_CHUNK(ch) do {                                                  \
    int term_ = (ch) >> 3;                                                    \
    int kc_ = ((ch) & 7) * KC;                                                \
    const __nv_bfloat16* Asrc_ = (term_ < 2) ? g_hi : g_lo;                   \
    const __nv_bfloat16* Bsrc_ = (term_ == 1) ? g_lo : g_hi;                  \
    uint32_t base_ = sb + ((ch) & 1) * STG;                                   \
    _Pragma("unroll")                                                         \
    for (int i_ = 0; i_ < 8; i_++) {                                          \
        int ci_ = tid + i_ * 256;                                             \
        int isB_ = ci_ >> 10;                                                 \
        int cj_ = ci_ & 1023;                                                 \
        int r_ = cj_ >> 3, c_ = cj_ & 7;                                      \
        const __nv_bfloat16* gp_ = isB_ ? Bsrc_ : Asrc_;                      \
        int grow_ = (isB_ ? bn : bm) + r_;                                    \
        uint32_t dst_ = base_ + isB_ * A_STG + SWZ(r_ * 128 + c_ * 16);       \
        const void* src_ = gp_ + (size_t)grow_ * DIM + kc_ + c_ * 8;          \
        asm volatile("cp.async.cg.shared.global [%0], [%1], 16;"              \
                     :: "r"(dst_), "l"(src_) : "memory");                     \
    }                                                                         \
    asm volatile("cp.async.commit_group;" ::: "memory");                      \
} while (0)

    ISSUE_CHUNK(0);
    for (int ch = 0; ch < 24; ch++) {
        if (ch + 1 < 24) {
            ISSUE_CHUNK(ch + 1);
            asm volatile("cp.async.wait_group 1;" ::: "memory");
        } else {
            asm volatile("cp.async.wait_group 0;" ::: "memory");
        }
        __syncthreads();

        const uint32_t Ab = sb + (ch & 1) * STG;
        const uint32_t Bb = Ab + A_STG;
#pragma unroll
        for (int kk = 0; kk < 4; kk++) {
            uint32_t a[2][4];
#pragma unroll
            for (int mi = 0; mi < 2; mi++) {
                uint32_t addr = Ab + SWZ((arow + mi * 16) * 128 + kk * 32 + akb);
                LDSMX4(a[mi][0], a[mi][1], a[mi][2], a[mi][3], addr);
            }
            uint32_t b[4][4];
#pragma unroll
            for (int p = 0; p < 4; p++) {
                uint32_t addr = Bb + SWZ((brow + p * 16) * 128 + kk * 32 + bkb);
                LDSMX4(b[p][0], b[p][1], b[p][2], b[p][3], addr);
            }
#pragma unroll
            for (int mi = 0; mi < 2; mi++)
#pragma unroll
                for (int ni = 0; ni < 8; ni++)
                    MMA16816(acc[mi][ni], a[mi], b[ni >> 1][(ni & 1) * 2],
                             b[ni >> 1][(ni & 1) * 2 + 1]);
        }
        __syncthreads();
    }

    // ---------------- epilogue: stage to smem, write tile (+mirror) --------
    float* Cs = (float*)smem;
    {
        const int r0 = wm * 32 + (lane >> 2);
        const int c0 = wn * 64 + 2 * (lane & 3);
#pragma unroll
        for (int mi = 0; mi < 2; mi++)
#pragma unroll
            for (int ni = 0; ni < 8; ni++) {
                int rr = r0 + mi * 16;
                int cc = c0 + ni * 8;
                Cs[rr * CS_PITCH + cc]           = acc[mi][ni][0];
                Cs[rr * CS_PITCH + cc + 1]       = acc[mi][ni][1];
                Cs[(rr + 8) * CS_PITCH + cc]     = acc[mi][ni][2];
                Cs[(rr + 8) * CS_PITCH + cc + 1] = acc[mi][ni][3];
            }
    }
    __syncthreads();

    // normal write: C[bm+r][bn+c]
    {
        const int c = tid & 127;
        const int rh = tid >> 7;          // 0/1
#pragma unroll 4
        for (int it = 0; it < 64; it++) {
            int r = it * 2 + rh;
            int gr = bm + r, gc = bn + c;
            if (gr < N && gc < N)
                C[(size_t)gr * N + gc] = Cs[r * CS_PITCH + c];
        }
    }
    // mirrored write: C[bn+c][bm+r]
    if (bi != bj) {
        const int r = tid & 127;
        const int ch2 = tid >> 7;
#pragma unroll 4
        for (int it = 0; it < 64; it++) {
            int c = it * 2 + ch2;
            int gr = bn + c, gc = bm + r;
            if (gr < N && gc < N)
                C[(size_t)gr * N + gc] = Cs[r * CS_PITCH + c];
        }
    }
}

// ------------------------- kernel 3: per-row top-21 select + transform -----
__device__ __forceinline__ unsigned f2ord(float f) {
    unsigned u = __float_as_uint(f);
    return (u & 0x80000000u) ? ~u : (u | 0x80000000u);
}

__global__ __launch_bounds__(256) void topk_kernel(float* __restrict__ C, int N)
{
    __shared__ float srow[MAXN];
    __shared__ int hist[256];
    __shared__ unsigned sh_prefix;
    __shared__ int sh_need;
    __shared__ int eq_idx[64];
    __shared__ int eq_cnt;
    __shared__ int sh_cutoff;

    const int row = blockIdx.x;
    const int t = threadIdx.x;
    float* rowp = C + (size_t)row * N;

    for (int j = t; j < N; j += 256) srow[j] = rowp[j];
    __syncthreads();

    unsigned prefix = 0;
    int need = KKEEP;
    const int iters = (N + 255) / 256;
    for (int rpass = 0; rpass < 4; rpass++) {
        int shift = 24 - 8 * rpass;
        hist[t] = 0;
        __syncthreads();
        unsigned pmask = (rpass == 0) ? 0u : (0xFFFFFFFFu << (shift + 8));
        for (int it = 0; it < iters; it++) {
            int j = t + it * 256;
            bool pred = (j < N) && ((f2ord(srow[j]) & pmask) == prefix);
            unsigned act = __ballot_sync(0xffffffffu, pred);
            if (pred) {
                int bin = (f2ord(srow[j]) >> shift) & 255;
                unsigned same = __match_any_sync(act, bin);
                if ((__ffs(same) - 1) == (t & 31))
                    atomicAdd(&hist[bin], __popc(same));
            }
        }
        __syncthreads();
        if (t == 0) {
            int cum = 0, b = 255;
            for (; b >= 0; b--) { cum += hist[b]; if (cum >= need) break; }
            int higher = cum - hist[b];
            sh_need = need - higher;
            sh_prefix = prefix | ((unsigned)b << shift);
        }
        __syncthreads();
        prefix = sh_prefix;
        need = sh_need;
        __syncthreads();
    }
    const unsigned kth = prefix;

    if (t == 0) { eq_cnt = 0; sh_cutoff = N; }
    __syncthreads();
    for (int j = t; j < N; j += 256) {
        if (f2ord(srow[j]) == kth) {
            int p = atomicAdd(&eq_cnt, 1);
            if (p < 64) eq_idx[p] = j;
        }
    }
    __syncthreads();
    if (t == 0) {
        int E = eq_cnt;
        if (E <= need) {
            sh_cutoff = N;
        } else if (E <= 64) {
            for (int a = 1; a < E; a++) {
                int v = eq_idx[a]; int b = a - 1;
                while (b >= 0 && eq_idx[b] > v) { eq_idx[b + 1] = eq_idx[b]; b--; }
                eq_idx[b + 1] = v;
            }
            sh_cutoff = eq_idx[need - 1];
        } else {
            int cnt = 0, cut = N;
            for (int j = 0; j < N; j++)
                if (f2ord(srow[j]) == kth) { if (++cnt == need) { cut = j; break; } }
            sh_cutoff = cut;
        }
    }
    __syncthreads();
    const int cutoff = sh_cutoff;

    const float CBASE = expf(-6.0f);
    for (int j = t; j < N; j += 256) {
        float s = srow[j];
        unsigned key = f2ord(s);
        bool keep = (key > kth) || (key == kth && j <= cutoff);
        float o;
        if (keep) {
            float xx = 6.0f * s - 6.0f;
            o = (xx > 0.f) ? (xx + 1.0f) : expf(xx);
        } else {
            o = CBASE;
        }
        rowp[j] = o;
    }
}

// ---------------------------------------------------------------------------
extern "C" void kernel_launch(void* const* d_in, const int* in_sizes, int n_in,
                              void* d_out, int out_size)
{
    const float* features = (const float*)d_in[0];
    const float* w0 = (const float*)d_in[1];
    const float* w1 = (const float*)d_in[2];
    float* out = (float*)d_out;

    int D = in_sizes[1];           // 512
    int N = in_sizes[0] / D;       // 10000
    (void)n_in; (void)out_size;

    norm_kernel<<<N, 128>>>(features, w0, w1, N);

    int nb = (N + 127) / 128;
    int npairs = nb * (nb + 1) / 2;
    cudaFuncSetAttribute(gemm_mma, cudaFuncAttributeMaxDynamicSharedMemorySize, GEMM_SMEM);
    gemm_mma<<<npairs, 256, GEMM_SMEM>>>(out, N);

    topk_kernel<<<N, 256>>>(out, N);
}